// round 11
// baseline (speedup 1.0000x reference)
#include <cuda_runtime.h>

#define C_DIM   64
#define TPB     128
#define MARGIN_F 0.01f
#define MAX_BLOCKS 8192

using u64 = unsigned long long;

// ---- compile-time weights ----
__host__ __device__ constexpr float W2f(int i)  { return 0.5f / (float)(C_DIM - i); }
__host__ __device__ constexpr float CPXf(int x) { return -(W2f(x + 1) + W2f(63 - x)); }
__host__ __device__ constexpr float W2SUMf() {
    float s = 0.0f;
    for (int i = 1; i < C_DIM; i++) s += W2f(i);
    return s;
}

__device__ float        g_partials[MAX_BLOCKS];
__device__ unsigned int g_sem = 0;

// ---- packed f32x2 helpers on float2 (keeps scalar halves addressable) ----
union F2U { float2 f; u64 u; };

__device__ __forceinline__ float2 fma2f(float2 a, float2 b, float2 c) {
    F2U ua, ub, uc, ur;
    ua.f = a; ub.f = b; uc.f = c;
    asm("fma.rn.f32x2 %0, %1, %2, %3;" : "=l"(ur.u) : "l"(ua.u), "l"(ub.u), "l"(uc.u));
    return ur.f;
}
__device__ __forceinline__ float2 add2f(float2 a, float2 b) {
    F2U ua, ub, ur;
    ua.f = a; ub.f = b;
    asm("add.rn.f32x2 %0, %1, %2;" : "=l"(ur.u) : "l"(ua.u), "l"(ub.u));
    return ur.f;
}
__device__ __forceinline__ float2 abs2f(float2 a) {
    F2U ua, ur;
    ua.f = a;
    asm("and.b64 %0, %1, 0x7FFFFFFF7FFFFFFF;" : "=l"(ur.u) : "l"(ua.u));
    return ur.f;
}

// 85-reg cap (65536 / (128*6*32) rounded): 6 CTAs/SM -> 24 warps, occ 37.5%.
// True demand ~80 regs (64 data + temps), so no spills expected.
__global__ void __launch_bounds__(TPB, 6)
margin_loss_kernel(const float* __restrict__ cand,
                   const float* __restrict__ summ,
                   float* __restrict__ out,
                   int B, float invB)
{
    const int row = blockIdx.x * TPB + threadIdx.x;

    float total = 0.0f;

    if (row < B) {
        float2 V[C_DIM / 2];

        const float4* rp = reinterpret_cast<const float4*>(cand + (size_t)row * C_DIM);
        const float s = summ[row];

        float sa = 0.0f;   // sum |cs - s|
        float p  = 0.0f;   // prefix sum of margin-folded values
        float an = 0.0f;   // telescoped analytic accumulator

        // ---- load + summary-abs + margin-fold + prefix, streamed ----
        #pragma unroll
        for (int i = 0; i < C_DIM / 4; i++) {
            float4 v = rp[i];
            float e[4] = { v.x, v.y, v.z, v.w };
            #pragma unroll
            for (int k = 0; k < 4; k++) {
                const int x = 4 * i + k;
                sa += fabsf(e[k] - s);                          // FADD + FADD|.|
                e[k] = __fmaf_rn(MARGIN_F, (float)x, e[k]);     // fold margin
                p += e[k];
                if (x < 63)
                    an = __fmaf_rn(CPXf(x), p, an);             // FFMA-imm
            }
            V[2 * i]     = make_float2(e[0], e[1]);
            V[2 * i + 1] = make_float2(e[2], e[3]);
        }

        // ---- analytic parts ----
        const float MOFF = 20.16f;   // sum_{x} 0.01*x
        total  = (sa + (p - MOFF) - 64.0f * s) * (0.5f / 64.0f);  // summary term
        total += an;
        total  = __fmaf_rn(p, W2SUMf(), total);                   // telescope

        const float2 NEG1 = make_float2(-1.0f, -1.0f);

        // ---- even gaps i = 2m: packed |V[g+m] - V[g]| ----
        #pragma unroll
        for (int m = 1; m < 32; m++) {
            float2 acc0 = make_float2(0.0f, 0.0f);
            float2 acc1 = make_float2(0.0f, 0.0f);
            #pragma unroll
            for (int g = 0; g + m < 32; g += 2) {
                acc0 = add2f(acc0, abs2f(fma2f(V[g], NEG1, V[g + m])));
                if (g + 1 + m < 32)
                    acc1 = add2f(acc1, abs2f(fma2f(V[g + 1], NEG1, V[g + 1 + m])));
            }
            float gsum = (acc0.x + acc0.y) + (acc1.x + acc1.y);
            total = __fmaf_rn(gsum, W2f(2 * m), total);           // FFMA-imm
        }

        // ---- odd gaps: scalar, |d| folded into FADD operand modifier ----
        // NOTE: macro parameter must not be named 'x' or 'y' (member access!)
        #define A_(idx) (((idx) & 1) ? V[(idx) >> 1].y : V[(idx) >> 1].x)
        #pragma unroll
        for (int i = 1; i < C_DIM; i += 2) {
            float c0 = 0.0f, c1 = 0.0f, c2 = 0.0f;
            #pragma unroll
            for (int j = 0; j + i < C_DIM; j += 3) {
                c0 += fabsf(A_(j + i) - A_(j));
                if (j + 1 + i < C_DIM) c1 += fabsf(A_(j + 1 + i) - A_(j + 1));
                if (j + 2 + i < C_DIM) c2 += fabsf(A_(j + 2 + i) - A_(j + 2));
            }
            total = __fmaf_rn((c0 + c1) + c2, W2f(i), total);     // FFMA-imm
        }
        #undef A_
    }

    // ---- deterministic block reduction ----
    __shared__ float sred[TPB];
    __shared__ bool  amLast;
    sred[threadIdx.x] = total;
    __syncthreads();
    #pragma unroll
    for (int off = TPB / 2; off > 0; off >>= 1) {
        if (threadIdx.x < off)
            sred[threadIdx.x] += sred[threadIdx.x + off];
        __syncthreads();
    }
    if (threadIdx.x == 0) {
        g_partials[blockIdx.x] = sred[0];
        __threadfence();
        unsigned int v = atomicAdd(&g_sem, 1u);
        amLast = (v == gridDim.x - 1);
    }
    __syncthreads();

    // ---- last arriving block: deterministic final reduce ----
    if (amLast) {
        float v = 0.0f;
        for (int i = threadIdx.x; i < (int)gridDim.x; i += TPB)
            v += g_partials[i];
        sred[threadIdx.x] = v;
        __syncthreads();
        #pragma unroll
        for (int off = TPB / 2; off > 0; off >>= 1) {
            if (threadIdx.x < off)
                sred[threadIdx.x] += sred[threadIdx.x + off];
            __syncthreads();
        }
        if (threadIdx.x == 0) {
            out[0] = sred[0] * invB;
            g_sem = 0;   // reset for next graph replay
        }
    }
}

extern "C" void kernel_launch(void* const* d_in, const int* in_sizes, int n_in,
                              void* d_out, int out_size)
{
    const float* cand = (const float*)d_in[0];   // [B, 64] f32
    const float* summ = (const float*)d_in[1];   // [B]     f32
    float* out = (float*)d_out;

    const int B = in_sizes[1];
    int nblocks = (B + TPB - 1) / TPB;
    if (nblocks > MAX_BLOCKS) nblocks = MAX_BLOCKS;
    const float invB = 1.0f / (float)B;

    margin_loss_kernel<<<nblocks, TPB>>>(cand, summ, out, B, invB);
}

// round 12
// speedup vs baseline: 1.2626x; 1.2626x over previous
#include <cuda_runtime.h>
#include <cuda_fp16.h>

#define C_DIM   64
#define TPB     128
#define MARGIN_F 0.01f
#define MAX_BLOCKS 8192

// Direct-relu per-gap weight: mean over (C - i) columns; 1/B applied at the end.
__host__ __device__ constexpr float W1f(int i) { return 1.0f / (float)(C_DIM - i); }

__device__ float        g_partials[MAX_BLOCKS];
__device__ unsigned int g_sem = 0;

// Two rows per thread: rows (2t, 2t+1) live in the (lo, hi) lanes of half2.
// 64 half2 = 64 registers of data -> no spills, no R6-style occupancy collapse.
__global__ void __launch_bounds__(TPB, 4)
margin_loss_kernel(const float* __restrict__ cand,
                   const float* __restrict__ summ,
                   float* __restrict__ out,
                   int B, float invB)
{
    const int t = blockIdx.x * TPB + threadIdx.x;
    const int rowA = 2 * t;
    const int rowB = 2 * t + 1;

    float thread_total = 0.0f;

    if (rowA < B) {
        const bool hasB = (rowB < B);
        const int  rB   = hasB ? rowB : rowA;

        const float4* pa = reinterpret_cast<const float4*>(cand + (size_t)rowA * C_DIM);
        const float4* pb = reinterpret_cast<const float4*>(cand + (size_t)rB   * C_DIM);

        const float sA = summ[rowA];
        const float sB = summ[rB];

        __half2 a2[C_DIM];
        float rsA = 0.0f, rsB = 0.0f;   // f32 summary relu sums

        // ---- load (f32), summary term (f32), margin fold (f32), cvt to half2 ----
        #pragma unroll
        for (int i4 = 0; i4 < C_DIM / 4; i4++) {
            float4 va = pa[i4];
            float4 vb = pb[i4];
            float ea[4] = { va.x, va.y, va.z, va.w };
            float eb[4] = { vb.x, vb.y, vb.z, vb.w };
            #pragma unroll
            for (int k = 0; k < 4; k++) {
                const int x = 4 * i4 + k;
                rsA += fmaxf(ea[k] - sA, 0.0f);
                rsB += fmaxf(eb[k] - sB, 0.0f);
                // fold margin so pair term becomes relu(a[k'] - a[j])
                float fa = __fmaf_rn(MARGIN_F, (float)x, ea[k]);
                float fb = __fmaf_rn(MARGIN_F, (float)x, eb[k]);
                a2[x] = __floats2half2_rn(fa, fb);
            }
        }

        float totalA = rsA * (1.0f / (float)C_DIM);
        float totalB = rsB * (1.0f / (float)C_DIM);

        const __half2 HZ = __floats2half2_rn(0.0f, 0.0f);

        // ---- all gaps, fully packed: one op covers the same (j, j+i) pair
        //      in BOTH rows. 4 rotating accumulators bound f16 rounding and
        //      give ILP. ----
        #pragma unroll
        for (int i = 1; i < C_DIM; i++) {
            __half2 c0 = HZ, c1 = HZ, c2 = HZ, c3 = HZ;
            #pragma unroll
            for (int j = 0; j + i < C_DIM; j += 4) {
                c0 = __hadd2(c0, __hmax2(__hsub2(a2[j + i], a2[j]), HZ));
                if (j + 1 + i < C_DIM)
                    c1 = __hadd2(c1, __hmax2(__hsub2(a2[j + 1 + i], a2[j + 1]), HZ));
                if (j + 2 + i < C_DIM)
                    c2 = __hadd2(c2, __hmax2(__hsub2(a2[j + 2 + i], a2[j + 2]), HZ));
                if (j + 3 + i < C_DIM)
                    c3 = __hadd2(c3, __hmax2(__hsub2(a2[j + 3 + i], a2[j + 3]), HZ));
            }
            __half2 tsum = __hadd2(__hadd2(c0, c1), __hadd2(c2, c3));
            totalA = __fmaf_rn(__low2float(tsum),  W1f(i), totalA);   // FFMA-imm
            totalB = __fmaf_rn(__high2float(tsum), W1f(i), totalB);
        }

        thread_total = totalA + (hasB ? totalB : 0.0f);
    }

    // ---- deterministic block reduction ----
    __shared__ float sred[TPB];
    __shared__ bool  amLast;
    sred[threadIdx.x] = thread_total;
    __syncthreads();
    #pragma unroll
    for (int off = TPB / 2; off > 0; off >>= 1) {
        if (threadIdx.x < off)
            sred[threadIdx.x] += sred[threadIdx.x + off];
        __syncthreads();
    }
    if (threadIdx.x == 0) {
        g_partials[blockIdx.x] = sred[0];
        __threadfence();
        unsigned int v = atomicAdd(&g_sem, 1u);
        amLast = (v == gridDim.x - 1);
    }
    __syncthreads();

    // ---- last arriving block: deterministic final reduce ----
    if (amLast) {
        float v = 0.0f;
        for (int i = threadIdx.x; i < (int)gridDim.x; i += TPB)
            v += g_partials[i];
        sred[threadIdx.x] = v;
        __syncthreads();
        #pragma unroll
        for (int off = TPB / 2; off > 0; off >>= 1) {
            if (threadIdx.x < off)
                sred[threadIdx.x] += sred[threadIdx.x + off];
            __syncthreads();
        }
        if (threadIdx.x == 0) {
            out[0] = sred[0] * invB;
            g_sem = 0;   // reset for next graph replay
        }
    }
}

extern "C" void kernel_launch(void* const* d_in, const int* in_sizes, int n_in,
                              void* d_out, int out_size)
{
    const float* cand = (const float*)d_in[0];   // [B, 64] f32
    const float* summ = (const float*)d_in[1];   // [B]     f32
    float* out = (float*)d_out;

    const int B = in_sizes[1];
    const int nthreads = (B + 1) / 2;            // 2 rows per thread
    int nblocks = (nthreads + TPB - 1) / TPB;
    if (nblocks > MAX_BLOCKS) nblocks = MAX_BLOCKS;
    const float invB = 1.0f / (float)B;

    margin_loss_kernel<<<nblocks, TPB>>>(cand, summ, out, B, invB);
}